// round 6
// baseline (speedup 1.0000x reference)
#include <cuda_runtime.h>

// L1Attn: attn[b,i,j,h] = -(1/sqrt(64)) * sum_w |q[b,j,h,w] - k[b,i,h,w]|
// q,k: [2, 512, 8, 64] fp32.  out: [2, 512(i=key), 512(j=query), 8] fp32.
//
// Design: 32x32 tile per block, 512 threads (2 warps per head, h uniform
// per warp), 4i x 4j register tile packed over w (f32x2), w chunked by 16.

#define NCTX 512
#define NH   8
#define WID  64
#define TI   32      // keys per block
#define TJ   32      // queries per block
#define WC   16      // w-chunk held in smem
#define RSTR 132     // chunk row stride: 8 heads * 16 w + 4 pad (== 4 mod 32 banks)
#define OSTR 260     // output staging row stride (16B aligned, == 4 mod 32 banks)

__device__ __forceinline__ unsigned long long addf32x2(unsigned long long a,
                                                       unsigned long long b) {
    unsigned long long r;
    asm("add.rn.f32x2 %0, %1, %2;" : "=l"(r) : "l"(a), "l"(b));
    return r;
}

__global__ void __launch_bounds__(512, 2)
l1attn_kernel(const float* __restrict__ q, const float* __restrict__ k,
              float* __restrict__ out) {
    // qs: 32 rows x RSTR = 4224 floats; ks same; total 8448 floats (33.8 KB).
    // Reused as output staging (needs 31*260+256 = 8316 <= 8448).
    __shared__ __align__(16) float smem[2 * TJ * RSTR];
    float* qs = smem;
    float* ks = smem + TJ * RSTR;   // holds -k

    const int tid = threadIdx.x;
    const int h   = tid >> 6;          // 0..7  (2 warps per head)
    const int l64 = tid & 63;
    const int jg  = l64 & 7;           // j = jg + 8*jj
    const int ig  = l64 >> 3;          // i = ig + 8*r

    const int j0 = blockIdx.x * TJ;
    const int i0 = blockIdx.y * TI;
    const int b  = blockIdx.z;

    const unsigned long long ABSM = 0x7FFFFFFF7FFFFFFFULL;

    unsigned long long acc[4][4];
#pragma unroll
    for (int r = 0; r < 4; r++)
#pragma unroll
        for (int jj = 0; jj < 4; jj++) acc[r][jj] = 0ULL;

    for (int c = 0; c < WID / WC; c++) {
        if (c) __syncthreads();
        const int wc = c * WC;
        // Cooperative chunk load: per tensor 32 rows x 8 heads x 16 w = 4096
        // floats = 1024 float4; 512 threads x 2 passes. Fully coalesced in gmem
        // (w innermost); STS.128 conflict-free (quarter covers 32 banks).
#pragma unroll
        for (int pass = 0; pass < 2; pass++) {
            int fidx = pass * 512 + tid;
            int w4   = fidx & 3;
            int hl   = (fidx >> 2) & 7;
            int row  = fidx >> 5;
            int so   = row * RSTR + hl * WC + w4 * 4;

            int goff = (((b * NCTX + j0 + row) * NH + hl) * WID) + wc + w4 * 4;
            *reinterpret_cast<float4*>(&qs[so]) =
                *reinterpret_cast<const float4*>(q + goff);

            int koff = (((b * NCTX + i0 + row) * NH + hl) * WID) + wc + w4 * 4;
            float4 kv4 = *reinterpret_cast<const float4*>(k + koff);
            kv4.x = -kv4.x; kv4.y = -kv4.y; kv4.z = -kv4.z; kv4.w = -kv4.w;
            *reinterpret_cast<float4*>(&ks[so]) = kv4;
        }
        __syncthreads();

#pragma unroll
        for (int w4 = 0; w4 < WC / 4; w4++) {
            // Load all 4 k-groups first (16 regs), stream q per jj (4 regs).
            unsigned long long kv[4][2];
#pragma unroll
            for (int r = 0; r < 4; r++) {
                ulonglong2 t = *reinterpret_cast<const ulonglong2*>(
                    &ks[(ig + 8 * r) * RSTR + h * WC + w4 * 4]);
                kv[r][0] = t.x; kv[r][1] = t.y;
            }
#pragma unroll
            for (int jj = 0; jj < 4; jj++) {
                ulonglong2 qv = *reinterpret_cast<const ulonglong2*>(
                    &qs[(jg + 8 * jj) * RSTR + h * WC + w4 * 4]);
#pragma unroll
                for (int r = 0; r < 4; r++) {
                    unsigned long long d0 = addf32x2(qv.x, kv[r][0]) & ABSM;
                    acc[r][jj] = addf32x2(acc[r][jj], d0);
                    unsigned long long d1 = addf32x2(qv.y, kv[r][1]) & ABSM;
                    acc[r][jj] = addf32x2(acc[r][jj], d1);
                }
            }
        }
    }

    __syncthreads();
    // Stage results in smem: stage[i][j*8+h], i-row = 256 contiguous out floats.
#pragma unroll
    for (int r = 0; r < 4; r++)
#pragma unroll
        for (int jj = 0; jj < 4; jj++) {
            float lo = __uint_as_float((unsigned int)(acc[r][jj] & 0xffffffffULL));
            float hi = __uint_as_float((unsigned int)(acc[r][jj] >> 32));
            float s  = (lo + hi) * -0.125f;   // -1/sqrt(64)
            int i = ig + 8 * r;
            int j = jg + 8 * jj;
            smem[i * OSTR + j * NH + h] = s;
        }
    __syncthreads();

    // Coalesced store: each of 32 i-rows is 256 contiguous floats = 64 float4.
#pragma unroll
    for (int pass = 0; pass < 4; pass++) {
        int sidx = pass * 512 + tid;       // 0..2047
        int c4   = sidx & 63;              // float4 index within row
        int i    = sidx >> 6;              // 0..31
        float4 v = *reinterpret_cast<const float4*>(&smem[i * OSTR + c4 * 4]);
        *reinterpret_cast<float4*>(
            out + (((b * NCTX + i0 + i) * NCTX + j0) * NH) + c4 * 4) = v;
    }
}

extern "C" void kernel_launch(void* const* d_in, const int* in_sizes, int n_in,
                              void* d_out, int out_size) {
    const float* q = (const float*)d_in[0];
    const float* k = (const float*)d_in[1];
    float* out = (float*)d_out;
    int bs = in_sizes[0] / (NCTX * NH * WID);   // = 2
    dim3 grid(NCTX / TJ, NCTX / TI, bs);
    l1attn_kernel<<<grid, 512>>>(q, k, out);
}

// round 7
// speedup vs baseline: 1.1587x; 1.1587x over previous
#include <cuda_runtime.h>

// L1Attn: attn[b,i,j,h] = -(1/sqrt(64)) * sum_w |q[b,j,h,w] - k[b,i,h,w]|
// q,k: [2, 512, 8, 64] fp32.  out: [2, 512(i=key), 512(j=query), 8] fp32.
//
// R7 design = proven R2 structure (16x16 tile, 256 thr, warp==head, 4i x 2j
// f32x2 register tile) with occupancy fixes: WC 32->16 (smem 33.8->16.9 KB)
// and __launch_bounds__(256,4) (regs 70->64) -> 4 CTAs/SM, 32 warps.

#define NCTX 512
#define NH   8
#define WID  64
#define TI   16      // keys per block
#define TJ   16      // queries per block
#define WC   16      // w-chunk held in smem
#define RSTR 132     // row stride: 8 heads * 16 w + 4 pad (== 4 mod 32 banks)
#define OSTR 132     // output staging row stride (16B aligned)

__device__ __forceinline__ unsigned long long addf32x2(unsigned long long a,
                                                       unsigned long long b) {
    unsigned long long r;
    asm("add.rn.f32x2 %0, %1, %2;" : "=l"(r) : "l"(a), "l"(b));
    return r;
}

__global__ void __launch_bounds__(256, 4)
l1attn_kernel(const float* __restrict__ q, const float* __restrict__ k,
              float* __restrict__ out) {
    // qs/ks: 16 rows x RSTR = 2112 floats each (8.4 KB each, 16.9 KB total).
    // qs reused as output staging (needs 15*132+128 = 2108 <= 2112).
    __shared__ __align__(16) float qs[TJ * RSTR];
    __shared__ __align__(16) float ks[TI * RSTR];   // holds -k

    const int tid = threadIdx.x;
    const int h   = tid >> 5;    // warp id == head
    const int sub = tid & 31;
    const int ig  = sub >> 3;    // 0..3  -> i = ig + 4*r
    const int jg  = sub & 7;     // 0..7  -> j = jg + 8*jj

    const int j0 = blockIdx.x * TJ;
    const int i0 = blockIdx.y * TI;
    const int b  = blockIdx.z;

    const unsigned long long ABSM = 0x7FFFFFFF7FFFFFFFULL;

    unsigned long long acc[4][2];
#pragma unroll
    for (int r = 0; r < 4; r++) { acc[r][0] = 0ULL; acc[r][1] = 0ULL; }

    for (int c = 0; c < WID / WC; c++) {
        if (c) __syncthreads();
        const int wc = c * WC;
        // Cooperative chunk load: per tensor 16 rows x 8 heads x 16 w = 2048
        // floats = 512 float4; 256 threads x 2 passes. Coalesced in gmem,
        // conflict-free STS.128 (each warp writes one 128-float row).
#pragma unroll
        for (int pass = 0; pass < 2; pass++) {
            int fidx = pass * 256 + tid;
            int w4   = fidx & 3;          // float4 index within w-chunk
            int hl   = (fidx >> 2) & 7;   // head
            int rl   = fidx >> 5;         // row within tile
            int so   = rl * RSTR + hl * WC + w4 * 4;

            int goff = (((b * NCTX + j0 + rl) * NH + hl) * WID) + wc + w4 * 4;
            *reinterpret_cast<float4*>(&qs[so]) =
                *reinterpret_cast<const float4*>(q + goff);

            int koff = (((b * NCTX + i0 + rl) * NH + hl) * WID) + wc + w4 * 4;
            float4 kv4 = *reinterpret_cast<const float4*>(k + koff);
            kv4.x = -kv4.x; kv4.y = -kv4.y; kv4.z = -kv4.z; kv4.w = -kv4.w;
            *reinterpret_cast<float4*>(&ks[so]) = kv4;
        }
        __syncthreads();

#pragma unroll
        for (int w4 = 0; w4 < WC / 4; w4++) {
            unsigned long long qv[2][2], kv[4][2];
#pragma unroll
            for (int jj = 0; jj < 2; jj++) {
                ulonglong2 t = *reinterpret_cast<const ulonglong2*>(
                    &qs[(jg + 8 * jj) * RSTR + h * WC + w4 * 4]);
                qv[jj][0] = t.x; qv[jj][1] = t.y;
            }
#pragma unroll
            for (int r = 0; r < 4; r++) {
                ulonglong2 t = *reinterpret_cast<const ulonglong2*>(
                    &ks[(ig + 4 * r) * RSTR + h * WC + w4 * 4]);
                kv[r][0] = t.x; kv[r][1] = t.y;
            }
#pragma unroll
            for (int r = 0; r < 4; r++)
#pragma unroll
                for (int jj = 0; jj < 2; jj++)
#pragma unroll
                    for (int p = 0; p < 2; p++) {
                        unsigned long long d = addf32x2(qv[jj][p], kv[r][p]);
                        d &= ABSM;                       // packed |x| (alu pipe)
                        acc[r][jj] = addf32x2(acc[r][jj], d);
                    }
        }
    }

    __syncthreads();
    // Stage results in smem (reuse qs): stage[i][j*8+h], i-row = 128 floats.
#pragma unroll
    for (int r = 0; r < 4; r++)
#pragma unroll
        for (int jj = 0; jj < 2; jj++) {
            float lo = __uint_as_float((unsigned int)(acc[r][jj] & 0xffffffffULL));
            float hi = __uint_as_float((unsigned int)(acc[r][jj] >> 32));
            float s  = (lo + hi) * -0.125f;   // -1/sqrt(64)
            int i = ig + 4 * r;
            int j = jg + 8 * jj;
            qs[i * OSTR + j * NH + h] = s;
        }
    __syncthreads();

    // Coalesced store: each of the 16 i-rows is 128 contiguous floats.
    {
        int i = tid >> 4;            // 0..15
        int c4 = (tid & 15) * 2;     // float4 index 0..30 step 2
        const float4* src = reinterpret_cast<const float4*>(&qs[i * OSTR + c4 * 4]);
        float4* dst = reinterpret_cast<float4*>(
            out + (((b * NCTX + i0 + i) * NCTX + j0) * NH) + c4 * 4);
        dst[0] = src[0];
        dst[1] = src[1];
    }
}

extern "C" void kernel_launch(void* const* d_in, const int* in_sizes, int n_in,
                              void* d_out, int out_size) {
    const float* q = (const float*)d_in[0];
    const float* k = (const float*)d_in[1];
    float* out = (float*)d_out;
    int bs = in_sizes[0] / (NCTX * NH * WID);   // = 2
    dim3 grid(NCTX / TJ, NCTX / TI, bs);
    l1attn_kernel<<<grid, 256>>>(q, k, out);
}